// round 4
// baseline (speedup 1.0000x reference)
#include <cuda_runtime.h>
#include <cstdint>

typedef unsigned long long u64;

#define N_ACT 80
#define M_CON 85
#define NP1   81
#define PDHG_ITERS 200
#define POWER_ITERS 20

// Per-problem shared block (one per CTA). All vector arrays 16B-aligned
// (sizes are multiples of 4 floats, struct base is 16B aligned).
struct PSmem {
    float vec[84];   // v / z_bar   (0..80 used; 81..83 zero)
    float y[88];     // Gv / y      (0..84 used)
    float x0[84];    // x0          (0..79 used; 80..83 zero pad for row_dot)
    float dv[84];    // x_hat - x0  (same padding)
    float d[88];     // row norms   (0..84 used)
    float red[8];    // per-warp reduction slots (warps 0..5)
    float As[M_CON * 81];  // pitch 81 (odd) -> conflict-free col reads at setup
};

// ---- packed f32x2 helpers ----
static __device__ __forceinline__ u64 pk(float lo, float hi) {
    u64 r; asm("mov.b64 %0, {%1, %2};" : "=l"(r) : "f"(lo), "f"(hi)); return r;
}
static __device__ __forceinline__ float2 up(u64 v) {
    float2 f; asm("mov.b64 {%0, %1}, %2;" : "=f"(f.x), "=f"(f.y) : "l"(v)); return f;
}
static __device__ __forceinline__ u64 ff2(u64 a, u64 b, u64 c) {
    u64 r; asm("fma.rn.f32x2 %0, %1, %2, %3;" : "=l"(r) : "l"(a), "l"(b), "l"(c)); return r;
}

static __device__ __forceinline__ float warp_sum(float v) {
    #pragma unroll
    for (int off = 16; off > 0; off >>= 1)
        v += __shfl_xor_sync(0xffffffffu, v, off);
    return v;
}
static __device__ __forceinline__ float warp_min(float v) {
    #pragma unroll
    for (int off = 16; off > 0; off >>= 1)
        v = fminf(v, __shfl_xor_sync(0xffffffffu, v, off));
    return v;
}

// dot over 81 terms: 80 from packed pairs GP[0..39] * V[0..79]  +  aux * V[80]
static __device__ __forceinline__ float row_dot(const u64* GP, float aux,
                                                const float* __restrict__ V) {
    const ulonglong2* v2 = reinterpret_cast<const ulonglong2*>(V);
    u64 a0 = 0, a1 = 0, a2 = 0, a3 = 0;
    #pragma unroll
    for (int q = 0; q < 20; q += 2) {
        ulonglong2 pa = v2[q];
        ulonglong2 pb = v2[q + 1];
        a0 = ff2(GP[2*q + 0], pa.x, a0);
        a1 = ff2(GP[2*q + 1], pa.y, a1);
        a2 = ff2(GP[2*q + 2], pb.x, a2);
        a3 = ff2(GP[2*q + 3], pb.y, a3);
    }
    float2 s0 = up(a0), s1 = up(a1), s2 = up(a2), s3 = up(a3);
    return ((s0.x + s0.y) + (s1.x + s1.y)) +
           ((s2.x + s2.y) + (s3.x + s3.y)) + aux * V[80];
}

// dot over 85 terms: 84 from packed pairs GP[0..41] * V[0..83]  +  aux * V[84]
static __device__ __forceinline__ float col_dot(const u64* GP, float aux,
                                                const float* __restrict__ V) {
    const ulonglong2* v2 = reinterpret_cast<const ulonglong2*>(V);
    u64 a0 = 0, a1 = 0, a2 = 0, a3 = 0;
    #pragma unroll
    for (int q = 0; q < 20; q += 2) {
        ulonglong2 pa = v2[q];
        ulonglong2 pb = v2[q + 1];
        a0 = ff2(GP[2*q + 0], pa.x, a0);
        a1 = ff2(GP[2*q + 1], pa.y, a1);
        a2 = ff2(GP[2*q + 2], pb.x, a2);
        a3 = ff2(GP[2*q + 3], pb.y, a3);
    }
    ulonglong2 pt = v2[20];
    a0 = ff2(GP[40], pt.x, a0);
    a1 = ff2(GP[41], pt.y, a1);
    float2 s0 = up(a0), s1 = up(a1), s2 = up(a2), s3 = up(a3);
    return ((s0.x + s0.y) + (s1.x + s1.y)) +
           ((s2.x + s2.y) + (s3.x + s3.y)) + aux * V[84];
}

__global__ __launch_bounds__(192, 3)
void acp_kernel(const float* __restrict__ xhat,
                const float* __restrict__ Aglob,
                const float* __restrict__ bglob,
                float* __restrict__ out)
{
    extern __shared__ __align__(16) float smem_raw[];
    PSmem* H = reinterpret_cast<PSmem*>(smem_raw);

    const int t    = threadIdx.x;          // 0..191
    const int lane = t & 31;
    const int wid  = t >> 5;               // 0..5
    const int prob = blockIdx.x;
    const bool isRow = (t < 96);
    const int r = t;                       // row index    (valid < 85)
    const int c = t - 96;                  // column index (valid < 81)

    const float* Ap = Aglob + (size_t)prob * (M_CON * N_ACT);

    // ---- stage A into shared (coalesced) ----
    for (int i = t; i < M_CON * N_ACT; i += 192) {
        int rr = i / N_ACT;
        int cc = i - rr * N_ACT;
        H->As[rr * 81 + cc] = Ap[i];
    }
    if (t < 88) H->y[t] = 0.0f;
    if (t < 84) H->vec[t] = (t < NP1) ? 1.0f : 0.0f;   // power-iter v0 = ones
    if (t >= 96 && t < 104) H->red[t - 96] = 0.0f;
    if (t >= 128 && t < 132) { H->x0[80 + (t - 128)] = 0.0f; H->dv[80 + (t - 128)] = 0.0f; }
    __syncthreads();

    // ---- per-thread packed G storage: one orientation per thread ----
    u64 GP[42];
    float aux  = 0.0f;   // row: d_r   | col: G[84][c]
    float bval = 0.0f;   // row workers only

    if (isRow) {
        if (r < M_CON) {
            const float* Ar = &H->As[r * 81];
            float s0 = 0.0f, s1 = 0.0f;
            #pragma unroll
            for (int k = 0; k < 40; k++) {
                float lo = Ar[2*k], hi = Ar[2*k + 1];
                GP[k] = pk(lo, hi);
                s0 = fmaf(lo, lo, s0);
                s1 = fmaf(hi, hi, s1);
            }
            aux = fmaxf(sqrtf(s0 + s1), 1e-12f);    // d_r = clip(||A_r||, 1e-12)
            H->d[r] = aux;
            bval = bglob[(size_t)prob * M_CON + r];
        }
        GP[40] = 0; GP[41] = 0;
    }
    __syncthreads();           // d[] ready for col workers
    if (!isRow && c < NP1) {
        if (c < N_ACT) {
            #pragma unroll
            for (int k = 0; k < 42; k++) {
                int j = 2 * k;
                GP[k] = pk(H->As[j * 81 + c], H->As[(j + 1) * 81 + c]);
            }
            aux = H->As[84 * 81 + c];
        } else {               // c == 80: column is d
            #pragma unroll
            for (int k = 0; k < 42; k++) {
                int j = 2 * k;
                GP[k] = pk(H->d[j], H->d[j + 1]);
            }
            aux = H->d[84];
        }
    }

    // ---- power iteration: v <- GT(G v) / ||.|| ----
    for (int pi = 0; pi < POWER_ITERS; pi++) {
        if (isRow && r < M_CON)
            H->y[r] = row_dot(GP, aux, H->vec);
        __syncthreads();
        float w = 0.0f;
        if (!isRow && c < NP1) w = col_dot(GP, aux, H->y);
        if (!isRow) {
            float ss = warp_sum(w * w);
            if (lane == 0) H->red[wid] = ss;
        }
        __syncthreads();
        if (!isRow && c < NP1) {
            float nrm = sqrtf(H->red[3] + H->red[4] + H->red[5]) + 1e-12f;
            H->vec[c] = w / nrm;
        }
        __syncthreads();
    }
    // L = ||G v||
    {
        float g2 = 0.0f;
        if (isRow && r < M_CON) {
            float g = row_dot(GP, aux, H->vec);
            g2 = g * g;
        }
        if (isRow) {
            float ss = warp_sum(g2);
            if (lane == 0) H->red[wid] = ss;
        }
        __syncthreads();
    }
    const float Lnrm = sqrtf(H->red[0] + H->red[1] + H->red[2]);
    const float tau  = 0.9f / fmaxf(Lnrm, 1e-6f);     // sigma == tau

    // ---- PDHG: 200 fixed iterations ----
    if (t < 88) H->y[t] = 0.0f;
    float zv = 0.0f, yv = 0.0f;
    __syncthreads();

    for (int it = 0; it < PDHG_ITERS; it++) {
        if (!isRow && c < NP1) {
            float gty = col_dot(GP, aux, H->y);
            float cterm = (c == N_ACT) ? -1.0f : 0.0f;
            float znew = fmaxf(zv - tau * (cterm + gty), 0.0f);
            H->vec[c] = 2.0f * znew - zv;     // extrapolated z_bar
            zv = znew;
        }
        __syncthreads();
        if (isRow && r < M_CON) {
            float gz = row_dot(GP, aux, H->vec);
            yv = fmaxf(yv + tau * (gz - bval), 0.0f);
            H->y[r] = yv;
        }
        __syncthreads();
    }

    // ---- alpha map ----
    if (!isRow && c < N_ACT) {
        H->x0[c] = zv;
        H->dv[c] = xhat[(size_t)prob * N_ACT + c] - zv;
    }
    __syncthreads();

    const float INF = __int_as_float(0x7f800000);
    float ai = INF;
    if (isRow && r < M_CON) {
        // x0/dv padded with zeros at [80..83] -> aux*V[80] term is harmless
        float ax0 = row_dot(GP, aux, H->x0);
        float ad  = row_dot(GP, aux, H->dv);
        float slack = fmaxf(bval - ax0, 0.0f);
        ai = (ad > 0.0f) ? (slack / (ad + 1e-12f)) : INF;
    }
    if (isRow) {
        ai = warp_min(ai);
        if (lane == 0) H->red[wid] = ai;
    }
    __syncthreads();
    float alpha = fminf(H->red[0], fminf(H->red[1], H->red[2]));
    if (!isfinite(alpha)) alpha = 1.0f;
    alpha = fminf(fmaxf(alpha - 1e-9f, 0.0f), 1.0f);

    if (!isRow && c < N_ACT)
        out[(size_t)prob * N_ACT + c] = fmaxf(H->x0[c] + alpha * H->dv[c], 0.0f);
}

extern "C" void kernel_launch(void* const* d_in, const int* in_sizes, int n_in,
                              void* d_out, int out_size)
{
    const float* xhat = (const float*)d_in[0];
    const float* A    = (const float*)d_in[1];
    const float* b    = (const float*)d_in[2];
    float* out        = (float*)d_out;
    int P = in_sizes[0] / N_ACT;            // 1024 problems

    size_t smem = sizeof(PSmem);            // ~28.6 KB per CTA
    cudaFuncSetAttribute(acp_kernel,
                         cudaFuncAttributeMaxDynamicSharedMemorySize,
                         (int)smem);

    acp_kernel<<<P, 192, smem>>>(xhat, A, b, out);
}

// round 6
// speedup vs baseline: 1.0907x; 1.0907x over previous
#include <cuda_runtime.h>
#include <cstdint>

#define N_ACT 80
#define M_CON 85
#define NP1   81
#define PDHG_ITERS 200
#define POWER_ITERS 20

__device__ __forceinline__ float warp_sum(float v) {
    #pragma unroll
    for (int off = 16; off > 0; off >>= 1)
        v += __shfl_xor_sync(0xffffffffu, v, off);
    return v;
}
__device__ __forceinline__ float warp_min(float v) {
    #pragma unroll
    for (int off = 16; off > 0; off >>= 1)
        v = fminf(v, __shfl_xor_sync(0xffffffffu, v, off));
    return v;
}

__global__ __launch_bounds__(128, 2)
void acp_kernel(const float* __restrict__ xhat,
                const float* __restrict__ Aglob,
                const float* __restrict__ bglob,
                float* __restrict__ out)
{
    __shared__ __align__(16) float sh_vec[84];   // v / z_bar   (0..80 used)
    __shared__ __align__(16) float sh_y[88];     // Gv / y      (0..84 used)
    __shared__ __align__(16) float sh_x0[80];
    __shared__ __align__(16) float sh_dv[80];
    __shared__ float sh_d[M_CON];
    __shared__ float sh_red[4];
    __shared__ float As[M_CON * 81];   // pitch 81 (odd) -> cheap column reads

    const int t    = threadIdx.x;      // 0..127
    const int lane = t & 31;
    const int wid  = t >> 5;           // 0..3
    // Interleaved mapping: each warp owns ~21 rows/cols -> all 4 SMSPs busy.
    const int idx  = 4 * lane + wid;   // 0..127
    const bool rowAct = (idx < M_CON);
    const bool colAct = (idx < NP1);
    const int prob = blockIdx.x;

    const float* Ap = Aglob + (size_t)prob * (M_CON * N_ACT);

    // ---- stage A into shared (coalesced) ----
    for (int i = t; i < M_CON * N_ACT; i += 128) {
        int rr = i / N_ACT;
        int cc = i - rr * N_ACT;
        As[rr * 81 + cc] = Ap[i];
    }
    if (t < 88) sh_y[t] = 0.0f;
    if (t < 84) sh_vec[t] = (t < NP1) ? 1.0f : 0.0f;   // power-iter v0 = ones
    if (t < 4) sh_red[t] = 0.0f;
    __syncthreads();

    // ---- register-resident G in both orientations (no spills @256-reg cap) ----
    float rowA[N_ACT];    // row idx of A     (rowAct)
    float colA[M_CON];    // column idx of G  (colAct; col 80 is d)
    float dval = 0.0f, bval = 0.0f;

    if (rowAct) {
        const float* Ar = &As[idx * 81];
        float s0 = 0.0f, s1 = 0.0f, s2 = 0.0f, s3 = 0.0f;
        #pragma unroll
        for (int k = 0; k < N_ACT; k += 4) {
            float a0 = Ar[k + 0], a1 = Ar[k + 1], a2 = Ar[k + 2], a3 = Ar[k + 3];
            rowA[k + 0] = a0; rowA[k + 1] = a1;
            rowA[k + 2] = a2; rowA[k + 3] = a3;
            s0 = fmaf(a0, a0, s0); s1 = fmaf(a1, a1, s1);
            s2 = fmaf(a2, a2, s2); s3 = fmaf(a3, a3, s3);
        }
        dval = fmaxf(sqrtf((s0 + s1) + (s2 + s3)), 1e-12f);
        sh_d[idx] = dval;
        bval = bglob[(size_t)prob * M_CON + idx];
    }
    __syncthreads();                       // sh_d ready for column 80
    if (colAct) {
        if (idx < N_ACT) {
            #pragma unroll
            for (int j = 0; j < M_CON; j++) colA[j] = As[j * 81 + idx];
        } else {                           // idx == 80: column is d
            #pragma unroll
            for (int j = 0; j < M_CON; j++) colA[j] = sh_d[j];
        }
    }

    // 81-term dot: rowA[0..79] . V[0..79] + dval * V[80]   (8 accumulators)
    #define ROW_DOT(res, VEC)                                              \
    {                                                                      \
        const float4* v4_ = reinterpret_cast<const float4*>(VEC);          \
        float a0=0.f,a1=0.f,a2=0.f,a3=0.f,a4=0.f,a5=0.f,a6=0.f,a7=0.f;     \
        _Pragma("unroll")                                                  \
        for (int q = 0; q < 10; q++) {                                     \
            float4 u = v4_[2*q], w = v4_[2*q+1];                           \
            a0 = fmaf(rowA[8*q+0], u.x, a0);                               \
            a1 = fmaf(rowA[8*q+1], u.y, a1);                               \
            a2 = fmaf(rowA[8*q+2], u.z, a2);                               \
            a3 = fmaf(rowA[8*q+3], u.w, a3);                               \
            a4 = fmaf(rowA[8*q+4], w.x, a4);                               \
            a5 = fmaf(rowA[8*q+5], w.y, a5);                               \
            a6 = fmaf(rowA[8*q+6], w.z, a6);                               \
            a7 = fmaf(rowA[8*q+7], w.w, a7);                               \
        }                                                                  \
        res = (((a0+a1)+(a2+a3)) + ((a4+a5)+(a6+a7))) + dval * (VEC)[80];  \
    }
    // 85-term dot: colA[0..84] . V[0..84]   (8 accumulators)
    #define COL_DOT(res, VEC)                                              \
    {                                                                      \
        const float4* v4_ = reinterpret_cast<const float4*>(VEC);          \
        float a0=0.f,a1=0.f,a2=0.f,a3=0.f,a4=0.f,a5=0.f,a6=0.f,a7=0.f;     \
        _Pragma("unroll")                                                  \
        for (int q = 0; q < 10; q++) {                                     \
            float4 u = v4_[2*q], w = v4_[2*q+1];                           \
            a0 = fmaf(colA[8*q+0], u.x, a0);                               \
            a1 = fmaf(colA[8*q+1], u.y, a1);                               \
            a2 = fmaf(colA[8*q+2], u.z, a2);                               \
            a3 = fmaf(colA[8*q+3], u.w, a3);                               \
            a4 = fmaf(colA[8*q+4], w.x, a4);                               \
            a5 = fmaf(colA[8*q+5], w.y, a5);                               \
            a6 = fmaf(colA[8*q+6], w.z, a6);                               \
            a7 = fmaf(colA[8*q+7], w.w, a7);                               \
        }                                                                  \
        float4 tl = v4_[20];                                               \
        a0 = fmaf(colA[80], tl.x, a0);                                     \
        a1 = fmaf(colA[81], tl.y, a1);                                     \
        a2 = fmaf(colA[82], tl.z, a2);                                     \
        a3 = fmaf(colA[83], tl.w, a3);                                     \
        res = (((a0+a1)+(a2+a3)) + ((a4+a5)+(a6+a7))) + colA[84]*(VEC)[84];\
    }

    // ---- power iteration: v <- GT(G v) / ||GT(G v)|| ----
    for (int pi = 0; pi < POWER_ITERS; pi++) {
        if (rowAct) {
            float g; ROW_DOT(g, sh_vec);
            sh_y[idx] = g;
        }
        __syncthreads();
        float w = 0.0f;
        if (colAct) { COL_DOT(w, sh_y); }
        float ss = warp_sum(w * w);
        if (lane == 0) sh_red[wid] = ss;
        __syncthreads();
        float nrm = sqrtf((sh_red[0] + sh_red[1]) + (sh_red[2] + sh_red[3])) + 1e-12f;
        if (colAct) sh_vec[idx] = w / nrm;
        __syncthreads();
    }
    // L = ||G v||
    {
        float g = 0.0f;
        if (rowAct) { ROW_DOT(g, sh_vec); }
        float ss = warp_sum(g * g);
        if (lane == 0) sh_red[wid] = ss;
        __syncthreads();
    }
    const float Lnrm = sqrtf((sh_red[0] + sh_red[1]) + (sh_red[2] + sh_red[3]));
    const float tau  = 0.9f / fmaxf(Lnrm, 1e-6f);     // sigma == tau

    // ---- PDHG: 200 fixed iterations ----
    if (t < 88) sh_y[t] = 0.0f;
    float zv = 0.0f, yv = 0.0f;
    const float cterm = (idx == N_ACT) ? -1.0f : 0.0f;
    __syncthreads();

    for (int it = 0; it < PDHG_ITERS; it++) {
        if (colAct) {
            float gty; COL_DOT(gty, sh_y);
            float znew = fmaxf(zv - tau * (cterm + gty), 0.0f);
            sh_vec[idx] = 2.0f * znew - zv;    // extrapolated z_bar
            zv = znew;
        }
        __syncthreads();
        if (rowAct) {
            float gz; ROW_DOT(gz, sh_vec);
            yv = fmaxf(yv + tau * (gz - bval), 0.0f);
            sh_y[idx] = yv;
        }
        __syncthreads();
    }

    // ---- alpha map ----
    if (idx < N_ACT) {
        sh_x0[idx] = zv;
        sh_dv[idx] = xhat[(size_t)prob * N_ACT + idx] - zv;
    }
    __syncthreads();

    const float INF = __int_as_float(0x7f800000);
    float ai = INF;
    if (rowAct) {
        float x0a = 0.0f, x0b = 0.0f, da = 0.0f, db = 0.0f;
        const float4* x4 = reinterpret_cast<const float4*>(sh_x0);
        const float4* d4 = reinterpret_cast<const float4*>(sh_dv);
        #pragma unroll
        for (int q = 0; q < 20; q++) {
            float4 xv = x4[q];
            float4 dv = d4[q];
            x0a = fmaf(rowA[4*q+0], xv.x, x0a);
            x0b = fmaf(rowA[4*q+1], xv.y, x0b);
            x0a = fmaf(rowA[4*q+2], xv.z, x0a);
            x0b = fmaf(rowA[4*q+3], xv.w, x0b);
            da  = fmaf(rowA[4*q+0], dv.x, da);
            db  = fmaf(rowA[4*q+1], dv.y, db);
            da  = fmaf(rowA[4*q+2], dv.z, da);
            db  = fmaf(rowA[4*q+3], dv.w, db);
        }
        float ax0 = x0a + x0b;
        float ad  = da + db;
        float slack = fmaxf(bval - ax0, 0.0f);
        ai = (ad > 0.0f) ? (slack / (ad + 1e-12f)) : INF;
    }
    ai = warp_min(ai);
    if (lane == 0) sh_red[wid] = ai;
    __syncthreads();
    float alpha = fminf(fminf(sh_red[0], sh_red[1]), fminf(sh_red[2], sh_red[3]));
    if (!isfinite(alpha)) alpha = 1.0f;
    alpha = fminf(fmaxf(alpha - 1e-9f, 0.0f), 1.0f);

    if (idx < N_ACT)
        out[(size_t)prob * N_ACT + idx] = fmaxf(sh_x0[idx] + alpha * sh_dv[idx], 0.0f);

    #undef ROW_DOT
    #undef COL_DOT
}

extern "C" void kernel_launch(void* const* d_in, const int* in_sizes, int n_in,
                              void* d_out, int out_size)
{
    const float* xhat = (const float*)d_in[0];
    const float* A    = (const float*)d_in[1];
    const float* b    = (const float*)d_in[2];
    float* out        = (float*)d_out;
    int P = in_sizes[0] / N_ACT;     // 1024 problems
    acp_kernel<<<P, 128>>>(xhat, A, b, out);
}

// round 8
// speedup vs baseline: 1.1562x; 1.0601x over previous
#include <cuda_runtime.h>
#include <cstdint>

typedef unsigned long long u64;

#define N_ACT 80
#define M_CON 85
#define NP1   81
#define PDHG_ITERS 200
#define POWER_ITERS 20

// ---- packed f32x2 helpers ----
static __device__ __forceinline__ u64 pk(float lo, float hi) {
    u64 r; asm("mov.b64 %0, {%1, %2};" : "=l"(r) : "f"(lo), "f"(hi)); return r;
}
static __device__ __forceinline__ float2 up(u64 v) {
    float2 f; asm("mov.b64 {%0, %1}, %2;" : "=f"(f.x), "=f"(f.y) : "l"(v)); return f;
}
static __device__ __forceinline__ u64 ff2(u64 a, u64 b, u64 c) {
    u64 r; asm("fma.rn.f32x2 %0, %1, %2, %3;" : "=l"(r) : "l"(a), "l"(b), "l"(c)); return r;
}

__device__ __forceinline__ float warp_sum(float v) {
    #pragma unroll
    for (int off = 16; off > 0; off >>= 1)
        v += __shfl_xor_sync(0xffffffffu, v, off);
    return v;
}
__device__ __forceinline__ float warp_min(float v) {
    #pragma unroll
    for (int off = 16; off > 0; off >>= 1)
        v = fminf(v, __shfl_xor_sync(0xffffffffu, v, off));
    return v;
}

__global__ __launch_bounds__(128, 2)
void acp_kernel(const float* __restrict__ xhat,
                const float* __restrict__ Aglob,
                const float* __restrict__ bglob,
                float* __restrict__ out)
{
    // 16B-aligned padded vectors; pads stay zero.
    __shared__ __align__(16) float sh_vec[84];   // v / z_bar  (0..80; 81..83 = 0)
    __shared__ __align__(16) float sh_y[88];     // Gv / y     (0..84; 85..87 = 0)
    __shared__ __align__(16) float sh_x0[84];    // x0         (0..79; 80..83 = 0)
    __shared__ __align__(16) float sh_dv[84];    // x_hat-x0   (0..79; 80..83 = 0)
    __shared__ float sh_d[M_CON];
    __shared__ float sh_red[4];
    __shared__ float As[M_CON * 81];   // pitch 81 (odd) -> cheap column reads

    const int t    = threadIdx.x;      // 0..127
    const int lane = t & 31;
    const int wid  = t >> 5;           // 0..3
    const int idx  = 4 * lane + wid;   // interleaved: all 4 SMSPs balanced
    const bool rowAct = (idx < M_CON);
    const bool colAct = (idx < NP1);
    const int prob = blockIdx.x;

    const float* Ap = Aglob + (size_t)prob * (M_CON * N_ACT);

    // ---- stage A into shared (coalesced) ----
    for (int i = t; i < M_CON * N_ACT; i += 128) {
        int rr = i / N_ACT;
        int cc = i - rr * N_ACT;
        As[rr * 81 + cc] = Ap[i];
    }
    if (t < 88) sh_y[t] = 0.0f;
    if (t < 84) { sh_vec[t] = (t < NP1) ? 1.0f : 0.0f; sh_x0[t] = 0.0f; sh_dv[t] = 0.0f; }
    if (t < 4) sh_red[t] = 0.0f;
    __syncthreads();

    // ---- register-resident G in both orientations, f32x2-packed ----
    u64 RP[40];            // row idx of A, 40 packed pairs (80 floats)
    u64 CP[42];            // column idx of G, j=0..83 packed (84 floats)
    float aux_c = 0.0f;    // G[84][idx]
    float dval = 0.0f, bval = 0.0f;

    if (rowAct) {
        const float* Ar = &As[idx * 81];
        float s0 = 0.0f, s1 = 0.0f;
        #pragma unroll
        for (int k = 0; k < 40; k++) {
            float lo = Ar[2*k], hi = Ar[2*k + 1];
            RP[k] = pk(lo, hi);
            s0 = fmaf(lo, lo, s0);
            s1 = fmaf(hi, hi, s1);
        }
        dval = fmaxf(sqrtf(s0 + s1), 1e-12f);   // d_r = clip(||A_r||, 1e-12)
        sh_d[idx] = dval;
        bval = bglob[(size_t)prob * M_CON + idx];
    }
    __syncthreads();                   // sh_d ready for column 80
    if (colAct) {
        if (idx < N_ACT) {
            #pragma unroll
            for (int k = 0; k < 42; k++)
                CP[k] = pk(As[(2*k) * 81 + idx], As[(2*k + 1) * 81 + idx]);
            aux_c = As[84 * 81 + idx];
        } else {                       // idx == 80: column is d
            #pragma unroll
            for (int k = 0; k < 42; k++)
                CP[k] = pk(sh_d[2*k], sh_d[2*k + 1]);
            aux_c = sh_d[84];
        }
    }

    // 81-term dot: RP (80 floats) . V[0..79]  +  dval * V[80]
    // ulonglong2 = 4 floats -> v2_[0..19] covers V[0..79].
    #define ROW_DOT(res, VEC)                                           \
    {                                                                   \
        const ulonglong2* v2_ = reinterpret_cast<const ulonglong2*>(VEC);\
        u64 q0 = 0, q1 = 0, q2 = 0, q3 = 0;                             \
        _Pragma("unroll")                                               \
        for (int q = 0; q < 20; q += 2) {                               \
            ulonglong2 pa = v2_[q];                                     \
            ulonglong2 pb = v2_[q + 1];                                 \
            q0 = ff2(RP[2*q + 0], pa.x, q0);                            \
            q1 = ff2(RP[2*q + 1], pa.y, q1);                            \
            q2 = ff2(RP[2*q + 2], pb.x, q2);                            \
            q3 = ff2(RP[2*q + 3], pb.y, q3);                            \
        }                                                               \
        float2 s0 = up(q0), s1 = up(q1), s2 = up(q2), s3 = up(q3);      \
        res = (((s0.x + s0.y) + (s1.x + s1.y)) +                        \
               ((s2.x + s2.y) + (s3.x + s3.y))) + dval * (VEC)[80];     \
    }
    // 85-term dot: CP (84 floats) . V[0..83]  +  aux_c * V[84]
    #define COL_DOT(res, VEC)                                           \
    {                                                                   \
        const ulonglong2* v2_ = reinterpret_cast<const ulonglong2*>(VEC);\
        u64 q0 = 0, q1 = 0, q2 = 0, q3 = 0;                             \
        _Pragma("unroll")                                               \
        for (int q = 0; q < 20; q += 2) {                               \
            ulonglong2 pa = v2_[q];                                     \
            ulonglong2 pb = v2_[q + 1];                                 \
            q0 = ff2(CP[2*q + 0], pa.x, q0);                            \
            q1 = ff2(CP[2*q + 1], pa.y, q1);                            \
            q2 = ff2(CP[2*q + 2], pb.x, q2);                            \
            q3 = ff2(CP[2*q + 3], pb.y, q3);                            \
        }                                                               \
        ulonglong2 pt = v2_[20];                                        \
        q0 = ff2(CP[40], pt.x, q0);                                     \
        q1 = ff2(CP[41], pt.y, q1);                                     \
        float2 s0 = up(q0), s1 = up(q1), s2 = up(q2), s3 = up(q3);      \
        res = (((s0.x + s0.y) + (s1.x + s1.y)) +                        \
               ((s2.x + s2.y) + (s3.x + s3.y))) + aux_c * (VEC)[84];    \
    }

    // ---- power iteration: v <- GT(G v) / ||GT(G v)|| ----
    for (int pi = 0; pi < POWER_ITERS; pi++) {
        if (rowAct) {
            float g; ROW_DOT(g, sh_vec);
            sh_y[idx] = g;
        }
        __syncthreads();
        float w = 0.0f;
        if (colAct) { COL_DOT(w, sh_y); }
        float ss = warp_sum(w * w);
        if (lane == 0) sh_red[wid] = ss;
        __syncthreads();
        float nrm = sqrtf((sh_red[0] + sh_red[1]) + (sh_red[2] + sh_red[3])) + 1e-12f;
        if (colAct) sh_vec[idx] = w / nrm;
        __syncthreads();
    }
    // L = ||G v||
    {
        float g = 0.0f;
        if (rowAct) { ROW_DOT(g, sh_vec); }
        float ss = warp_sum(g * g);
        if (lane == 0) sh_red[wid] = ss;
        __syncthreads();
    }
    const float Lnrm = sqrtf((sh_red[0] + sh_red[1]) + (sh_red[2] + sh_red[3]));
    const float tau  = 0.9f / fmaxf(Lnrm, 1e-6f);     // sigma == tau

    // ---- PDHG: 200 fixed iterations ----
    if (t < 88) sh_y[t] = 0.0f;
    float zv = 0.0f, yv = 0.0f;
    const float cterm = (idx == N_ACT) ? -1.0f : 0.0f;
    __syncthreads();

    for (int it = 0; it < PDHG_ITERS; it++) {
        if (colAct) {
            float gty; COL_DOT(gty, sh_y);
            float znew = fmaxf(zv - tau * (cterm + gty), 0.0f);
            sh_vec[idx] = 2.0f * znew - zv;    // extrapolated z_bar
            zv = znew;
        }
        __syncthreads();
        if (rowAct) {
            float gz; ROW_DOT(gz, sh_vec);
            yv = fmaxf(yv + tau * (gz - bval), 0.0f);
            sh_y[idx] = yv;
        }
        __syncthreads();
    }

    // ---- alpha map ----
    if (idx < N_ACT) {
        sh_x0[idx] = zv;
        sh_dv[idx] = xhat[(size_t)prob * N_ACT + idx] - zv;
    }
    __syncthreads();

    const float INF = __int_as_float(0x7f800000);
    float ai = INF;
    if (rowAct) {
        // x0/dv pads are zero -> dval*VEC[80] term vanishes: pure A-row dots.
        float ax0; ROW_DOT(ax0, sh_x0);
        float ad;  ROW_DOT(ad,  sh_dv);
        float slack = fmaxf(bval - ax0, 0.0f);
        ai = (ad > 0.0f) ? (slack / (ad + 1e-12f)) : INF;
    }
    ai = warp_min(ai);
    if (lane == 0) sh_red[wid] = ai;
    __syncthreads();
    float alpha = fminf(fminf(sh_red[0], sh_red[1]), fminf(sh_red[2], sh_red[3]));
    if (!isfinite(alpha)) alpha = 1.0f;
    alpha = fminf(fmaxf(alpha - 1e-9f, 0.0f), 1.0f);

    if (idx < N_ACT)
        out[(size_t)prob * N_ACT + idx] = fmaxf(sh_x0[idx] + alpha * sh_dv[idx], 0.0f);

    #undef ROW_DOT
    #undef COL_DOT
}

extern "C" void kernel_launch(void* const* d_in, const int* in_sizes, int n_in,
                              void* d_out, int out_size)
{
    const float* xhat = (const float*)d_in[0];
    const float* A    = (const float*)d_in[1];
    const float* b    = (const float*)d_in[2];
    float* out        = (float*)d_out;
    int P = in_sizes[0] / N_ACT;     // 1024 problems
    acp_kernel<<<P, 128>>>(xhat, A, b, out);
}

// round 9
// speedup vs baseline: 1.3435x; 1.1620x over previous
#include <cuda_runtime.h>
#include <cstdint>

typedef unsigned long long u64;

#define N_ACT 80
#define M_CON 85
#define NP1   81
#define PDHG_ITERS 200
#define POWER_ITERS 20

// ---- packed f32x2 helpers ----
static __device__ __forceinline__ u64 pk(float lo, float hi) {
    u64 r; asm("mov.b64 %0, {%1, %2};" : "=l"(r) : "f"(lo), "f"(hi)); return r;
}
static __device__ __forceinline__ float2 up(u64 v) {
    float2 f; asm("mov.b64 {%0, %1}, %2;" : "=f"(f.x), "=f"(f.y) : "l"(v)); return f;
}
static __device__ __forceinline__ u64 ff2(u64 a, u64 b, u64 c) {
    u64 r; asm("fma.rn.f32x2 %0, %1, %2, %3;" : "=l"(r) : "l"(a), "l"(b), "l"(c)); return r;
}

__device__ __forceinline__ float warp_sum(float v) {
    #pragma unroll
    for (int off = 16; off > 0; off >>= 1)
        v += __shfl_xor_sync(0xffffffffu, v, off);
    return v;
}
__device__ __forceinline__ float warp_min(float v) {
    #pragma unroll
    for (int off = 16; off > 0; off >>= 1)
        v = fminf(v, __shfl_xor_sync(0xffffffffu, v, off));
    return v;
}

// 44-float packed dot: G[22] (u64 pairs) . V-half (11 ulonglong2 = 44 floats)
__device__ __forceinline__ float dot44(const u64* __restrict__ G,
                                       const ulonglong2* __restrict__ v2) {
    u64 a0 = 0, a1 = 0, a2 = 0, a3 = 0;
    #pragma unroll
    for (int q = 0; q < 10; q += 2) {
        ulonglong2 pa = v2[q];
        ulonglong2 pb = v2[q + 1];
        a0 = ff2(G[2*q + 0], pa.x, a0);
        a1 = ff2(G[2*q + 1], pa.y, a1);
        a2 = ff2(G[2*q + 2], pb.x, a2);
        a3 = ff2(G[2*q + 3], pb.y, a3);
    }
    ulonglong2 pt = v2[10];
    a0 = ff2(G[20], pt.x, a0);
    a1 = ff2(G[21], pt.y, a1);
    float2 s0 = up(a0), s1 = up(a1), s2 = up(a2), s3 = up(a3);
    return ((s0.x + s0.y) + (s1.x + s1.y)) + ((s2.x + s2.y) + (s3.x + s3.y));
}

__global__ __launch_bounds__(256, 2)
void acp_kernel(const float* __restrict__ xhat,
                const float* __restrict__ Aglob,
                const float* __restrict__ bglob,
                float* __restrict__ out)
{
    // All vectors padded to 88 floats (22 ulonglong2); pads are hard zeros.
    __shared__ __align__(16) float sh_vec[88];   // v / z_bar (0..80)
    __shared__ __align__(16) float sh_y[88];     // Gv / y    (0..84)
    __shared__ __align__(16) float sh_x0[88];    // x0        (0..79)
    __shared__ __align__(16) float sh_dv[88];    // x_hat-x0  (0..79)
    __shared__ __align__(16) float sh_d[88];     // row norms (0..84)
    __shared__ float sh_red[8];
    __shared__ float As[M_CON * 81];             // pitch 81

    const int t    = threadIdx.x;        // 0..255
    const int lane = t & 31;
    const int wid  = t >> 5;             // 0..7
    const int part = lane & 1;           // pair = lanes (2k, 2k+1)
    const int idx  = (lane >> 1) * 8 + wid;   // 0..127, interleaved over warps
    const bool rowAct = (idx < M_CON);
    const bool colAct = (idx < NP1);
    const int prob = blockIdx.x;

    // ---- stage A into shared (coalesced) ----
    {
        const float* Ap = Aglob + (size_t)prob * (M_CON * N_ACT);
        for (int i = t; i < M_CON * N_ACT; i += 256) {
            int rr = i / N_ACT;
            int cc = i - rr * N_ACT;
            As[rr * 81 + cc] = Ap[i];
        }
    }
    if (t < 88) {
        sh_y[t]  = 0.0f;
        sh_vec[t] = (t < NP1) ? 1.0f : 0.0f;   // power-iter v0 = ones
        sh_x0[t] = 0.0f;
        sh_dv[t] = 0.0f;
        sh_d[t]  = 0.0f;
    }
    __syncthreads();

    // ---- per-thread packed halves ----
    u64 RP[22];        // row half: part0 = A[idx][0..43]; part1 = A[idx][44..79], slot80=d, rest 0
    u64 CP[22];        // col half: part p = G[44p .. 44p+43][idx] (zeros past 84)
    float bval = 0.0f;

    #pragma unroll
    for (int k = 0; k < 22; k++) { RP[k] = 0; CP[k] = 0; }

    // row fill + norm (shfl hoisted to warp scope)
    {
        float ss = 0.0f;
        if (rowAct) {
            const float* Ar = &As[idx * 81];
            if (part == 0) {
                #pragma unroll
                for (int k = 0; k < 22; k++) {
                    float lo = Ar[2*k], hi = Ar[2*k + 1];
                    RP[k] = pk(lo, hi);
                    ss = fmaf(lo, lo, fmaf(hi, hi, ss));
                }
            } else {
                #pragma unroll
                for (int k = 0; k < 18; k++) {
                    float lo = Ar[44 + 2*k], hi = Ar[45 + 2*k];
                    RP[k] = pk(lo, hi);
                    ss = fmaf(lo, lo, fmaf(hi, hi, ss));
                }
            }
        }
        float tot = ss + __shfl_xor_sync(0xffffffffu, ss, 1);
        if (rowAct) {
            float dval = fmaxf(sqrtf(tot), 1e-12f);
            if (part == 1) RP[18] = pk(dval, 0.0f);   // element 80 of row-G
            if (part == 0) sh_d[idx] = dval;
            bval = bglob[(size_t)prob * M_CON + idx];
        }
    }
    __syncthreads();                       // sh_d complete (pads still zero)

    // col fill
    if (colAct) {
        if (idx < N_ACT) {
            if (part == 0) {
                #pragma unroll
                for (int k = 0; k < 22; k++)
                    CP[k] = pk(As[(2*k) * 81 + idx], As[(2*k + 1) * 81 + idx]);
            } else {
                #pragma unroll
                for (int k = 0; k < 20; k++)
                    CP[k] = pk(As[(44 + 2*k) * 81 + idx], As[(45 + 2*k) * 81 + idx]);
                CP[20] = pk(As[84 * 81 + idx], 0.0f);  // j = 84 (+ zero)
            }
        } else {   // idx == 80: column is d (sh_d zero-padded to 88)
            #pragma unroll
            for (int k = 0; k < 22; k++)
                CP[k] = pk(sh_d[44 * part + 2*k], sh_d[44 * part + 2*k + 1]);
        }
    }

    const ulonglong2* vecV = reinterpret_cast<const ulonglong2*>(sh_vec) + 11 * part;
    const ulonglong2* yV   = reinterpret_cast<const ulonglong2*>(sh_y)   + 11 * part;

    // ---- power iteration: v <- GT(G v) / ||GT(G v)|| ----
    for (int pi = 0; pi < POWER_ITERS; pi++) {
        float pr = dot44(RP, vecV);                     // zero for inactive
        float g  = pr + __shfl_xor_sync(0xffffffffu, pr, 1);
        if (rowAct && part == 0) sh_y[idx] = g;
        __syncthreads();
        float pc = dot44(CP, yV);
        float w  = pc + __shfl_xor_sync(0xffffffffu, pc, 1);
        float ss = warp_sum((colAct && part == 0) ? w * w : 0.0f);
        if (lane == 0) sh_red[wid] = ss;
        __syncthreads();
        float nrm = sqrtf(((sh_red[0] + sh_red[1]) + (sh_red[2] + sh_red[3])) +
                          ((sh_red[4] + sh_red[5]) + (sh_red[6] + sh_red[7]))) + 1e-12f;
        if (colAct && part == 0) sh_vec[idx] = w / nrm;
        __syncthreads();
    }
    // L = ||G v||
    {
        float pr = dot44(RP, vecV);
        float g  = pr + __shfl_xor_sync(0xffffffffu, pr, 1);
        float ss = warp_sum((rowAct && part == 0) ? g * g : 0.0f);
        if (lane == 0) sh_red[wid] = ss;
        __syncthreads();
    }
    const float Lnrm = sqrtf(((sh_red[0] + sh_red[1]) + (sh_red[2] + sh_red[3])) +
                             ((sh_red[4] + sh_red[5]) + (sh_red[6] + sh_red[7])));
    const float tau  = 0.9f / fmaxf(Lnrm, 1e-6f);       // sigma == tau

    // ---- PDHG: 200 fixed iterations ----
    if (t < 88) sh_y[t] = 0.0f;
    float zv = 0.0f, yv = 0.0f;
    const float cterm = (idx == N_ACT) ? -1.0f : 0.0f;
    __syncthreads();

    for (int it = 0; it < PDHG_ITERS; it++) {
        float pc  = dot44(CP, yV);
        float gty = pc + __shfl_xor_sync(0xffffffffu, pc, 1);
        float znew = fmaxf(zv - tau * (cterm + gty), 0.0f);
        if (colAct && part == 0) sh_vec[idx] = 2.0f * znew - zv;   // z_bar
        zv = znew;
        __syncthreads();
        float pr = dot44(RP, vecV);
        float gz = pr + __shfl_xor_sync(0xffffffffu, pr, 1);
        yv = fmaxf(yv + tau * (gz - bval), 0.0f);
        if (rowAct && part == 0) sh_y[idx] = yv;
        __syncthreads();
    }

    // ---- alpha map ----
    if (idx < N_ACT && part == 0) {
        sh_x0[idx] = zv;
        sh_dv[idx] = xhat[(size_t)prob * N_ACT + idx] - zv;
    }
    __syncthreads();

    const float INF = __int_as_float(0x7f800000);
    float ai;
    {
        // sh_x0/sh_dv pads (incl. slot 80) are zero -> RP's dval term vanishes.
        const ulonglong2* x0V = reinterpret_cast<const ulonglong2*>(sh_x0) + 11 * part;
        const ulonglong2* dvV = reinterpret_cast<const ulonglong2*>(sh_dv) + 11 * part;
        float p0 = dot44(RP, x0V);
        float p1 = dot44(RP, dvV);
        float ax0 = p0 + __shfl_xor_sync(0xffffffffu, p0, 1);
        float ad  = p1 + __shfl_xor_sync(0xffffffffu, p1, 1);
        if (rowAct) {
            float slack = fmaxf(bval - ax0, 0.0f);
            ai = (ad > 0.0f) ? (slack / (ad + 1e-12f)) : INF;
        } else {
            ai = INF;
        }
    }
    ai = warp_min(ai);
    if (lane == 0) sh_red[wid] = ai;
    __syncthreads();
    float alpha = fminf(fminf(fminf(sh_red[0], sh_red[1]), fminf(sh_red[2], sh_red[3])),
                        fminf(fminf(sh_red[4], sh_red[5]), fminf(sh_red[6], sh_red[7])));
    if (!isfinite(alpha)) alpha = 1.0f;
    alpha = fminf(fmaxf(alpha - 1e-9f, 0.0f), 1.0f);

    if (idx < N_ACT && part == 0)
        out[(size_t)prob * N_ACT + idx] = fmaxf(sh_x0[idx] + alpha * sh_dv[idx], 0.0f);
}

extern "C" void kernel_launch(void* const* d_in, const int* in_sizes, int n_in,
                              void* d_out, int out_size)
{
    const float* xhat = (const float*)d_in[0];
    const float* A    = (const float*)d_in[1];
    const float* b    = (const float*)d_in[2];
    float* out        = (float*)d_out;
    int P = in_sizes[0] / N_ACT;     // 1024 problems
    acp_kernel<<<P, 256>>>(xhat, A, b, out);
}

// round 10
// speedup vs baseline: 1.3802x; 1.0273x over previous
#include <cuda_runtime.h>
#include <cstdint>

typedef unsigned long long u64;

#define N_ACT 80
#define M_CON 85
#define NP1   81
#define PDHG_ITERS 200
#define POWER_ITERS 20

// ---- packed f32x2 helpers ----
static __device__ __forceinline__ u64 pk(float lo, float hi) {
    u64 r; asm("mov.b64 %0, {%1, %2};" : "=l"(r) : "f"(lo), "f"(hi)); return r;
}
static __device__ __forceinline__ float2 up(u64 v) {
    float2 f; asm("mov.b64 {%0, %1}, %2;" : "=f"(f.x), "=f"(f.y) : "l"(v)); return f;
}
static __device__ __forceinline__ u64 ff2(u64 a, u64 b, u64 c) {
    u64 r; asm("fma.rn.f32x2 %0, %1, %2, %3;" : "=l"(r) : "l"(a), "l"(b), "l"(c)); return r;
}
static __device__ __forceinline__ u64 add2(u64 a, u64 b) {
    u64 r; asm("add.rn.f32x2 %0, %1, %2;" : "=l"(r) : "l"(a), "l"(b)); return r;
}

__device__ __forceinline__ float warp_sum(float v) {
    #pragma unroll
    for (int off = 16; off > 0; off >>= 1)
        v += __shfl_xor_sync(0xffffffffu, v, off);
    return v;
}
__device__ __forceinline__ float warp_min(float v) {
    #pragma unroll
    for (int off = 16; off > 0; off >>= 1)
        v = fminf(v, __shfl_xor_sync(0xffffffffu, v, off));
    return v;
}

// 44-float packed dot: G[22] (u64 pairs) . V-half (11 ulonglong2 = 44 floats)
// Combine uses packed adds: 3x add.rn.f32x2 + 1 FADD (vs 7 scalar FADD).
__device__ __forceinline__ float dot44(const u64* __restrict__ G,
                                       const ulonglong2* __restrict__ v2) {
    u64 a0 = 0, a1 = 0, a2 = 0, a3 = 0;
    #pragma unroll
    for (int q = 0; q < 10; q += 2) {
        ulonglong2 pa = v2[q];
        ulonglong2 pb = v2[q + 1];
        a0 = ff2(G[2*q + 0], pa.x, a0);
        a1 = ff2(G[2*q + 1], pa.y, a1);
        a2 = ff2(G[2*q + 2], pb.x, a2);
        a3 = ff2(G[2*q + 3], pb.y, a3);
    }
    ulonglong2 pt = v2[10];
    a0 = ff2(G[20], pt.x, a0);
    a1 = ff2(G[21], pt.y, a1);
    u64 s = add2(add2(a0, a1), add2(a2, a3));
    float2 f = up(s);
    return f.x + f.y;
}

__global__ __launch_bounds__(256, 2)
void acp_kernel(const float* __restrict__ xhat,
                const float* __restrict__ Aglob,
                const float* __restrict__ bglob,
                float* __restrict__ out)
{
    // All vectors padded to 88 floats (22 ulonglong2); pads are hard zeros.
    __shared__ __align__(16) float sh_vec[88];   // v / z_bar (0..80)
    __shared__ __align__(16) float sh_y[88];     // Gv / y    (0..84)
    __shared__ __align__(16) float sh_x0[88];    // x0        (0..79)
    __shared__ __align__(16) float sh_dv[88];    // x_hat-x0  (0..79)
    __shared__ __align__(16) float sh_d[88];     // row norms (0..84)
    __shared__ float sh_red[8];
    __shared__ float As[M_CON * 81];             // pitch 81

    const int t    = threadIdx.x;        // 0..255
    const int lane = t & 31;
    const int wid  = t >> 5;             // 0..7
    const int part = lane & 1;           // pair = lanes (2k, 2k+1)
    const int idx  = (lane >> 1) * 8 + wid;   // 0..127, interleaved over warps
    const bool rowAct = (idx < M_CON);
    const bool colAct = (idx < NP1);
    const int prob = blockIdx.x;

    // ---- stage A into shared (coalesced) ----
    {
        const float* Ap = Aglob + (size_t)prob * (M_CON * N_ACT);
        for (int i = t; i < M_CON * N_ACT; i += 256) {
            int rr = i / N_ACT;
            int cc = i - rr * N_ACT;
            As[rr * 81 + cc] = Ap[i];
        }
    }
    if (t < 88) {
        sh_y[t]  = 0.0f;
        sh_vec[t] = (t < NP1) ? 1.0f : 0.0f;   // power-iter v0 = ones
        sh_x0[t] = 0.0f;
        sh_dv[t] = 0.0f;
        sh_d[t]  = 0.0f;
    }
    __syncthreads();

    // ---- per-thread packed halves ----
    u64 RP[22];        // row half: part0 = A[idx][0..43]; part1 = A[idx][44..79], slot80=d, rest 0
    u64 CP[22];        // col half: part p = G[44p .. 44p+43][idx] (zeros past 84)
    float bval = 0.0f;

    #pragma unroll
    for (int k = 0; k < 22; k++) { RP[k] = 0; CP[k] = 0; }

    // row fill + norm (shfl hoisted to warp scope)
    {
        float ss = 0.0f;
        if (rowAct) {
            const float* Ar = &As[idx * 81];
            if (part == 0) {
                #pragma unroll
                for (int k = 0; k < 22; k++) {
                    float lo = Ar[2*k], hi = Ar[2*k + 1];
                    RP[k] = pk(lo, hi);
                    ss = fmaf(lo, lo, fmaf(hi, hi, ss));
                }
            } else {
                #pragma unroll
                for (int k = 0; k < 18; k++) {
                    float lo = Ar[44 + 2*k], hi = Ar[45 + 2*k];
                    RP[k] = pk(lo, hi);
                    ss = fmaf(lo, lo, fmaf(hi, hi, ss));
                }
            }
        }
        float tot = ss + __shfl_xor_sync(0xffffffffu, ss, 1);
        if (rowAct) {
            float dval = fmaxf(sqrtf(tot), 1e-12f);
            if (part == 1) RP[18] = pk(dval, 0.0f);   // element 80 of row-G
            if (part == 0) sh_d[idx] = dval;
            bval = bglob[(size_t)prob * M_CON + idx];
        }
    }
    __syncthreads();                       // sh_d complete (pads still zero)

    // col fill
    if (colAct) {
        if (idx < N_ACT) {
            if (part == 0) {
                #pragma unroll
                for (int k = 0; k < 22; k++)
                    CP[k] = pk(As[(2*k) * 81 + idx], As[(2*k + 1) * 81 + idx]);
            } else {
                #pragma unroll
                for (int k = 0; k < 20; k++)
                    CP[k] = pk(As[(44 + 2*k) * 81 + idx], As[(45 + 2*k) * 81 + idx]);
                CP[20] = pk(As[84 * 81 + idx], 0.0f);  // j = 84 (+ zero)
            }
        } else {   // idx == 80: column is d (sh_d zero-padded to 88)
            #pragma unroll
            for (int k = 0; k < 22; k++)
                CP[k] = pk(sh_d[44 * part + 2*k], sh_d[44 * part + 2*k + 1]);
        }
    }

    const ulonglong2* vecV = reinterpret_cast<const ulonglong2*>(sh_vec) + 11 * part;
    const ulonglong2* yV   = reinterpret_cast<const ulonglong2*>(sh_y)   + 11 * part;

    // ---- power iteration: v <- GT(G v), normalize every 3rd iter + last ----
    // Direction is normalization-invariant; scale bounded: L^2 <= ~1.5e4,
    // 3 unnormalized iters -> ||v|| <= ~3e13, sum(w^2) <= ~7e28 << FLT_MAX.
    for (int pi = 0; pi < POWER_ITERS; pi++) {
        float pr = dot44(RP, vecV);                     // zero for inactive
        float g  = pr + __shfl_xor_sync(0xffffffffu, pr, 1);
        if (rowAct && part == 0) sh_y[idx] = g;
        __syncthreads();
        float pc = dot44(CP, yV);
        float w  = pc + __shfl_xor_sync(0xffffffffu, pc, 1);
        const bool norm_now = ((pi % 3) == 2) || (pi == POWER_ITERS - 1);
        if (norm_now) {
            float ss = warp_sum((colAct && part == 0) ? w * w : 0.0f);
            if (lane == 0) sh_red[wid] = ss;
            __syncthreads();
            float nrm = sqrtf(((sh_red[0] + sh_red[1]) + (sh_red[2] + sh_red[3])) +
                              ((sh_red[4] + sh_red[5]) + (sh_red[6] + sh_red[7]))) + 1e-12f;
            if (colAct && part == 0) sh_vec[idx] = w / nrm;
        } else {
            if (colAct && part == 0) sh_vec[idx] = w;
        }
        __syncthreads();
    }
    // L = ||G v||   (v is normalized: last power iter normalizes)
    {
        float pr = dot44(RP, vecV);
        float g  = pr + __shfl_xor_sync(0xffffffffu, pr, 1);
        float ss = warp_sum((rowAct && part == 0) ? g * g : 0.0f);
        if (lane == 0) sh_red[wid] = ss;
        __syncthreads();
    }
    const float Lnrm = sqrtf(((sh_red[0] + sh_red[1]) + (sh_red[2] + sh_red[3])) +
                             ((sh_red[4] + sh_red[5]) + (sh_red[6] + sh_red[7])));
    const float tau  = 0.9f / fmaxf(Lnrm, 1e-6f);       // sigma == tau

    // ---- PDHG: 200 fixed iterations ----
    if (t < 88) sh_y[t] = 0.0f;
    float zv = 0.0f, yv = 0.0f;
    const float cterm = (idx == N_ACT) ? -1.0f : 0.0f;
    __syncthreads();

    for (int it = 0; it < PDHG_ITERS; it++) {
        float pc  = dot44(CP, yV);
        float gty = pc + __shfl_xor_sync(0xffffffffu, pc, 1);
        float znew = fmaxf(zv - tau * (cterm + gty), 0.0f);
        if (colAct && part == 0) sh_vec[idx] = 2.0f * znew - zv;   // z_bar
        zv = znew;
        __syncthreads();
        float pr = dot44(RP, vecV);
        float gz = pr + __shfl_xor_sync(0xffffffffu, pr, 1);
        yv = fmaxf(yv + tau * (gz - bval), 0.0f);
        if (rowAct && part == 0) sh_y[idx] = yv;
        __syncthreads();
    }

    // ---- alpha map ----
    if (idx < N_ACT && part == 0) {
        sh_x0[idx] = zv;
        sh_dv[idx] = xhat[(size_t)prob * N_ACT + idx] - zv;
    }
    __syncthreads();

    const float INF = __int_as_float(0x7f800000);
    float ai;
    {
        // sh_x0/sh_dv pads (incl. slot 80) are zero -> RP's dval term vanishes.
        const ulonglong2* x0V = reinterpret_cast<const ulonglong2*>(sh_x0) + 11 * part;
        const ulonglong2* dvV = reinterpret_cast<const ulonglong2*>(sh_dv) + 11 * part;
        float p0 = dot44(RP, x0V);
        float p1 = dot44(RP, dvV);
        float ax0 = p0 + __shfl_xor_sync(0xffffffffu, p0, 1);
        float ad  = p1 + __shfl_xor_sync(0xffffffffu, p1, 1);
        if (rowAct) {
            float slack = fmaxf(bval - ax0, 0.0f);
            ai = (ad > 0.0f) ? (slack / (ad + 1e-12f)) : INF;
        } else {
            ai = INF;
        }
    }
    ai = warp_min(ai);
    if (lane == 0) sh_red[wid] = ai;
    __syncthreads();
    float alpha = fminf(fminf(fminf(sh_red[0], sh_red[1]), fminf(sh_red[2], sh_red[3])),
                        fminf(fminf(sh_red[4], sh_red[5]), fminf(sh_red[6], sh_red[7])));
    if (!isfinite(alpha)) alpha = 1.0f;
    alpha = fminf(fmaxf(alpha - 1e-9f, 0.0f), 1.0f);

    if (idx < N_ACT && part == 0)
        out[(size_t)prob * N_ACT + idx] = fmaxf(sh_x0[idx] + alpha * sh_dv[idx], 0.0f);
}

extern "C" void kernel_launch(void* const* d_in, const int* in_sizes, int n_in,
                              void* d_out, int out_size)
{
    const float* xhat = (const float*)d_in[0];
    const float* A    = (const float*)d_in[1];
    const float* b    = (const float*)d_in[2];
    float* out        = (float*)d_out;
    int P = in_sizes[0] / N_ACT;     // 1024 problems
    acp_kernel<<<P, 256>>>(xhat, A, b, out);
}